// round 1
// baseline (speedup 1.0000x reference)
#include <cuda_runtime.h>
#include <cstdint>

// Problem constants (fixed by the reference)
#define N_NEUR 50000
#define DD     5
#define NB     5
#define DT_C   1.0f
#define BATCH  4
#define E_REC  2000000
#define E_LGN  600000
#define E_BKG  200000
#define NLGN   17400
#define NBKG   100

#define BN        (BATCH * N_NEUR)           // 200000
#define BNNB      (BATCH * N_NEUR * NB)      // 1000000
#define BND       (BATCH * N_NEUR * DD)      // 1000000

// Output layout (floats): z | v | r | asc1 | asc2 | psc_rise | psc | buf
#define OFF_Z    0
#define OFF_V    (BN)
#define OFF_R    (2*BN)
#define OFF_A1   (3*BN)
#define OFF_A2   (4*BN)
#define OFF_PR   (5*BN)                      // 1,000,000
#define OFF_PSC  (5*BN + BNNB)               // 2,000,000
#define OFF_BUF  (5*BN + 2*BNNB)             // 3,000,000

// ---------------------------------------------------------------------------
// Kernel A: initialize new_psc_rise output with syn_decay[k] * psc_rise[b,n,k].
// The scatter kernels then atomicAdd psc_initial[k]*contrib on top.
// ---------------------------------------------------------------------------
__global__ void init_psc_rise_kernel(const float* __restrict__ psc_rise,
                                     const float* __restrict__ syn_decay,
                                     float* __restrict__ out_pr)
{
    int idx = blockIdx.x * blockDim.x + threadIdx.x;
    if (idx >= BNNB) return;
    int k = idx % NB;
    out_pr[idx] = __ldg(syn_decay + k) * psc_rise[idx];
}

// ---------------------------------------------------------------------------
// Kernel B: edge scatter. One thread per edge; loops over 4 batches.
// z sources are binary spikes (0/1) with low firing rates, so most edges
// short-circuit before touching factors or doing atomics.
// ---------------------------------------------------------------------------
__global__ void scatter_kernel(const float* __restrict__ z, int z_stride,
                               const int*   __restrict__ pre,
                               const int*   __restrict__ post,
                               const float* __restrict__ w,
                               const float* __restrict__ factors,
                               const float* __restrict__ psc_initial,
                               float* __restrict__ out_pr,
                               int n_edges)
{
    int e = blockIdx.x * blockDim.x + threadIdx.x;
    if (e >= n_edges) return;

    int p = __ldg(pre + e);
    float z0 = __ldg(z + 0 * z_stride + p);
    float z1 = __ldg(z + 1 * z_stride + p);
    float z2 = __ldg(z + 2 * z_stride + p);
    float z3 = __ldg(z + 3 * z_stride + p);

    if ((z0 + z1 + z2 + z3) == 0.0f) return;   // no batch fired on this edge

    float we = __ldg(w + e);
    int   q  = __ldg(post + e);

    float c[NB];
#pragma unroll
    for (int k = 0; k < NB; k++)
        c[k] = we * __ldg(factors + (size_t)e * NB + k) * __ldg(psc_initial + k);

    float zb[BATCH] = {z0, z1, z2, z3};
#pragma unroll
    for (int b = 0; b < BATCH; b++) {
        if (zb[b] != 0.0f) {
            float* base = out_pr + (size_t)b * N_NEUR * NB + (size_t)q * NB;
#pragma unroll
            for (int k = 0; k < NB; k++)
                atomicAdd(base + k, zb[b] * c[k]);
        }
    }
}

// ---------------------------------------------------------------------------
// Kernel C: per-(b,n) neuron state update + new_psc + front of new_buf.
// Note: new_psc depends only on OLD psc/psc_rise (not syn_in), and c1 uses
// the OLD asc_1/asc_2 values.
// ---------------------------------------------------------------------------
__global__ void neuron_kernel(const float* __restrict__ z_buf,
                              const float* __restrict__ v,
                              const float* __restrict__ r,
                              const float* __restrict__ asc1,
                              const float* __restrict__ asc2,
                              const float* __restrict__ psc_rise,
                              const float* __restrict__ psc,
                              const float* __restrict__ decay,
                              const float* __restrict__ current_factor,
                              const float* __restrict__ v_th,
                              const float* __restrict__ v_reset,
                              const float* __restrict__ e_l,
                              const float* __restrict__ g,
                              const float* __restrict__ t_ref,
                              const float* __restrict__ asc_amps,
                              const float* __restrict__ exp_dt_k,
                              const float* __restrict__ syn_decay,
                              float* __restrict__ out)
{
    int idx = blockIdx.x * blockDim.x + threadIdx.x;   // b*N + n
    if (idx >= BN) return;
    int b = idx / N_NEUR;
    int n = idx - b * N_NEUR;

    // new_psc[k] = syn_decay[k] * (psc[k] + DT*psc_rise[k]); input_current = sum_k
    size_t po = (size_t)idx * NB;
    float input_current = 0.0f;
#pragma unroll
    for (int k = 0; k < NB; k++) {
        float np = __ldg(syn_decay + k) * (psc[po + k] + DT_C * psc_rise[po + k]);
        out[OFF_PSC + po + k] = np;
        input_current += np;
    }

    float prev_z = z_buf[(size_t)b * N_NEUR * DD + n];

    float a1 = asc1[idx];
    float a2 = asc2[idx];
    float na1 = __ldg(exp_dt_k + 2 * n + 0) * a1 + prev_z * __ldg(asc_amps + 2 * n + 0);
    float na2 = __ldg(exp_dt_k + 2 * n + 1) * a2 + prev_z * __ldg(asc_amps + 2 * n + 1);

    float eln = __ldg(e_l + n);
    float c1  = input_current + a1 + a2 + __ldg(g + n) * eln;
    float nv  = __ldg(decay + n) * v[idx] + __ldg(current_factor + n) * c1;
    if (prev_z > 0.0f) nv = __ldg(v_reset + n);

    float nr = fmaxf(r[idx] + prev_z * __ldg(t_ref + n) - DT_C, 0.0f);

    float vth = __ldg(v_th + n);
    float vsc = (nv - vth) / (vth - eln + 1e-16f);
    float nz  = (vsc > 0.0f && nr <= 0.0f) ? 1.0f : 0.0f;

    out[OFF_Z  + idx] = nz;
    out[OFF_V  + idx] = nv;
    out[OFF_R  + idx] = nr;
    out[OFF_A1 + idx] = na1;
    out[OFF_A2 + idx] = na2;
    out[OFF_BUF + (size_t)b * N_NEUR * DD + n] = nz;   // new_buf[:, :N] = new_z
}

// ---------------------------------------------------------------------------
// Kernel D: buffer shift — new_buf[:, N:] = z_buf[:, :N*(D-1)]
// ---------------------------------------------------------------------------
__global__ void buf_shift_kernel(const float* __restrict__ z_buf,
                                 float* __restrict__ out)
{
    int idx = blockIdx.x * blockDim.x + threadIdx.x;
    const int per_b = N_NEUR * (DD - 1);
    if (idx >= BATCH * per_b) return;
    int b = idx / per_b;
    int i = idx - b * per_b;
    out[OFF_BUF + (size_t)b * N_NEUR * DD + N_NEUR + i] =
        z_buf[(size_t)b * N_NEUR * DD + i];
}

// ---------------------------------------------------------------------------
extern "C" void kernel_launch(void* const* d_in, const int* in_sizes, int n_in,
                              void* d_out, int out_size)
{
    const float* z_buf          = (const float*)d_in[0];
    const float* v              = (const float*)d_in[1];
    const float* r              = (const float*)d_in[2];
    const float* asc_1          = (const float*)d_in[3];
    const float* asc_2          = (const float*)d_in[4];
    const float* psc_rise       = (const float*)d_in[5];
    const float* psc            = (const float*)d_in[6];
    const float* lgn_x          = (const float*)d_in[7];
    const float* bkg_x          = (const float*)d_in[8];
    const float* rec_w          = (const float*)d_in[9];
    const float* rec_factors    = (const float*)d_in[10];
    const float* lgn_w          = (const float*)d_in[11];
    const float* lgn_factors    = (const float*)d_in[12];
    const float* bkg_w          = (const float*)d_in[13];
    const float* bkg_factors    = (const float*)d_in[14];
    const float* decay          = (const float*)d_in[15];
    const float* current_factor = (const float*)d_in[16];
    const float* v_th           = (const float*)d_in[17];
    const float* v_reset        = (const float*)d_in[18];
    const float* e_l            = (const float*)d_in[19];
    const float* g              = (const float*)d_in[20];
    const float* t_ref          = (const float*)d_in[21];
    const float* asc_amps       = (const float*)d_in[22];
    const float* exp_dt_k       = (const float*)d_in[23];
    const float* syn_decay      = (const float*)d_in[24];
    const float* psc_initial    = (const float*)d_in[25];
    const int*   rec_pre        = (const int*)d_in[26];
    const int*   rec_post       = (const int*)d_in[27];
    const int*   lgn_pre        = (const int*)d_in[28];
    const int*   lgn_post       = (const int*)d_in[29];
    const int*   bkg_pre        = (const int*)d_in[30];
    const int*   bkg_post       = (const int*)d_in[31];

    float* out = (float*)d_out;

    const int T = 256;

    // 1) new_psc_rise = syn_decay * psc_rise  (scatter targets this region)
    init_psc_rise_kernel<<<(BNNB + T - 1) / T, T>>>(psc_rise, syn_decay, out + OFF_PR);

    // 2) synaptic scatter: rec (pre indexes z_buf over N*D), lgn, bkg
    scatter_kernel<<<(E_REC + T - 1) / T, T>>>(z_buf, N_NEUR * DD,
                                               rec_pre, rec_post, rec_w, rec_factors,
                                               psc_initial, out + OFF_PR, E_REC);
    scatter_kernel<<<(E_LGN + T - 1) / T, T>>>(lgn_x, NLGN,
                                               lgn_pre, lgn_post, lgn_w, lgn_factors,
                                               psc_initial, out + OFF_PR, E_LGN);
    scatter_kernel<<<(E_BKG + T - 1) / T, T>>>(bkg_x, NBKG,
                                               bkg_pre, bkg_post, bkg_w, bkg_factors,
                                               psc_initial, out + OFF_PR, E_BKG);

    // 3) neuron state update (independent of scatter results — only needs old state)
    neuron_kernel<<<(BN + T - 1) / T, T>>>(z_buf, v, r, asc_1, asc_2,
                                           psc_rise, psc,
                                           decay, current_factor, v_th, v_reset,
                                           e_l, g, t_ref, asc_amps, exp_dt_k,
                                           syn_decay, out);

    // 4) buffer shift
    buf_shift_kernel<<<(BATCH * N_NEUR * (DD - 1) + T - 1) / T, T>>>(z_buf, out);
}

// round 4
// speedup vs baseline: 1.1498x; 1.1498x over previous
#include <cuda_runtime.h>
#include <cstdint>

// Problem constants (fixed by the reference)
#define N_NEUR 50000
#define DD     5
#define NB     5
#define DT_C   1.0f
#define BATCH  4
#define E_REC  2000000
#define E_LGN  600000
#define E_BKG  200000
#define NLGN   17400
#define NBKG   100

#define BN        (BATCH * N_NEUR)           // 200000
#define BNNB      (BATCH * N_NEUR * NB)      // 1000000

// Output layout (floats): z | v | r | asc1 | asc2 | psc_rise | psc | buf
#define OFF_Z    0
#define OFF_V    (BN)
#define OFF_R    (2*BN)
#define OFF_A1   (3*BN)
#define OFF_A2   (4*BN)
#define OFF_PR   (5*BN)
#define OFF_PSC  (5*BN + BNNB)
#define OFF_BUF  (5*BN + 2*BNNB)

#define E_TOTAL  (E_REC + E_LGN + E_BKG)     // 2,800,000 (divisible by 4)

// ---------------------------------------------------------------------------
// Fused elementwise kernel: one thread per (b, n).
//  - new_psc_rise init: out_pr = syn_decay * psc_rise   (scatter adds on top)
//  - new_psc = syn_decay * (psc + DT*psc_rise); input_current = sum_k
//  - GLIF neuron state update (uses OLD asc1/asc2 in c1)
//  - new_buf[:, :N] = new_z ; new_buf[:, N:] = z_buf[:, :4N]
// ---------------------------------------------------------------------------
__global__ void __launch_bounds__(256)
fused_elementwise_kernel(const float* __restrict__ z_buf,
                         const float* __restrict__ v,
                         const float* __restrict__ r,
                         const float* __restrict__ asc1,
                         const float* __restrict__ asc2,
                         const float* __restrict__ psc_rise,
                         const float* __restrict__ psc,
                         const float* __restrict__ decay,
                         const float* __restrict__ current_factor,
                         const float* __restrict__ v_th,
                         const float* __restrict__ v_reset,
                         const float* __restrict__ e_l,
                         const float* __restrict__ g,
                         const float* __restrict__ t_ref,
                         const float* __restrict__ asc_amps,
                         const float* __restrict__ exp_dt_k,
                         const float* __restrict__ syn_decay,
                         float* __restrict__ out)
{
    int idx = blockIdx.x * blockDim.x + threadIdx.x;   // b*N + n
    if (idx >= BN) return;
    int b = idx / N_NEUR;
    int n = idx - b * N_NEUR;

    float sd[NB];
#pragma unroll
    for (int k = 0; k < NB; k++) sd[k] = __ldg(syn_decay + k);

    // psc block: init psc_rise output + new_psc + input current
    size_t po = (size_t)idx * NB;
    float input_current = 0.0f;
#pragma unroll
    for (int k = 0; k < NB; k++) {
        float pr = psc_rise[po + k];
        float pc = psc[po + k];
        out[OFF_PR  + po + k] = sd[k] * pr;               // scatter target
        float np = sd[k] * (pc + DT_C * pr);
        out[OFF_PSC + po + k] = np;
        input_current += np;
    }

    size_t zb_base = (size_t)b * N_NEUR * DD;
    float prev_z = z_buf[zb_base + n];

    float a1 = asc1[idx];
    float a2 = asc2[idx];
    float na1 = __ldg(exp_dt_k + 2 * n + 0) * a1 + prev_z * __ldg(asc_amps + 2 * n + 0);
    float na2 = __ldg(exp_dt_k + 2 * n + 1) * a2 + prev_z * __ldg(asc_amps + 2 * n + 1);

    float eln = __ldg(e_l + n);
    float c1  = input_current + a1 + a2 + __ldg(g + n) * eln;
    float nv  = __ldg(decay + n) * v[idx] + __ldg(current_factor + n) * c1;
    if (prev_z > 0.0f) nv = __ldg(v_reset + n);

    float nr = fmaxf(r[idx] + prev_z * __ldg(t_ref + n) - DT_C, 0.0f);

    float vth = __ldg(v_th + n);
    float vsc = (nv - vth) / (vth - eln + 1e-16f);
    float nz  = (vsc > 0.0f && nr <= 0.0f) ? 1.0f : 0.0f;

    out[OFF_Z  + idx] = nz;
    out[OFF_V  + idx] = nv;
    out[OFF_R  + idx] = nr;
    out[OFF_A1 + idx] = na1;
    out[OFF_A2 + idx] = na2;

    // new_buf: front = new_z, rest shifted (all coalesced)
    out[OFF_BUF + zb_base + n] = nz;
#pragma unroll
    for (int d = 0; d < DD - 1; d++)
        out[OFF_BUF + zb_base + (d + 1) * N_NEUR + n] = z_buf[zb_base + d * N_NEUR + n];
}

// ---------------------------------------------------------------------------
// Unified scatter: one launch covering rec | lgn | bkg segments.
// Segment boundaries (2.0M, 2.6M edges) are multiples of 1024 edges = 256
// quads, so the segment branch is uniform per block — no intra-warp
// divergence on the selector.
// 4 edges per thread via 16B vector loads (el is always a multiple of 4 in
// every segment, so int4/float4 accesses are aligned).
// Spikes are exactly 0.0f or 1.0f (rec_z = 0.4*z + 0.6*z == z in fp32),
// so a firing batch contributes exactly c[k] — no multiply needed.
// ---------------------------------------------------------------------------
__global__ void __launch_bounds__(256)
scatter_all_kernel(const float* __restrict__ z_rec,   // z_buf, stride N*D
                   const float* __restrict__ z_lgn,   // stride NLGN
                   const float* __restrict__ z_bkg,   // stride NBKG
                   const int*   __restrict__ rp, const int* __restrict__ rq,
                   const float* __restrict__ rw, const float* __restrict__ rf,
                   const int*   __restrict__ lp, const int* __restrict__ lq,
                   const float* __restrict__ lw, const float* __restrict__ lf,
                   const int*   __restrict__ bp, const int* __restrict__ bq,
                   const float* __restrict__ bw, const float* __restrict__ bf,
                   const float* __restrict__ psc_initial,
                   float* __restrict__ out_pr)
{
    int quad = blockIdx.x * blockDim.x + threadIdx.x;
    int e = quad * 4;
    if (e >= E_TOTAL) return;

    const int* pre; const int* post; const float* w; const float* f;
    const float* z; int zs; int el;
    if (e < E_REC)               { pre = rp; post = rq; w = rw; f = rf; z = z_rec; zs = N_NEUR * DD; el = e; }
    else if (e < E_REC + E_LGN)  { pre = lp; post = lq; w = lw; f = lf; z = z_lgn; zs = NLGN;        el = e - E_REC; }
    else                         { pre = bp; post = bq; w = bw; f = bf; z = z_bkg; zs = NBKG;        el = e - E_REC - E_LGN; }

    int4 p4 = *reinterpret_cast<const int4*>(pre + el);
    int pe[4] = {p4.x, p4.y, p4.z, p4.w};

    // gather spikes for 4 edges x 4 batches (binary, low firing rate)
    float zv[16];
#pragma unroll
    for (int j = 0; j < 4; j++)
#pragma unroll
        for (int b = 0; b < BATCH; b++)
            zv[j * 4 + b] = __ldg(z + (size_t)b * zs + pe[j]);

    float zsum[4];
#pragma unroll
    for (int j = 0; j < 4; j++)
        zsum[j] = zv[j*4+0] + zv[j*4+1] + zv[j*4+2] + zv[j*4+3];

    if ((zsum[0] + zsum[1] + zsum[2] + zsum[3]) == 0.0f) return;

    int4   q4 = *reinterpret_cast<const int4*>(post + el);
    float4 w4 = *reinterpret_cast<const float4*>(w + el);
    int   qe[4] = {q4.x, q4.y, q4.z, q4.w};
    float we[4] = {w4.x, w4.y, w4.z, w4.w};

    float pi[NB];
#pragma unroll
    for (int k = 0; k < NB; k++) pi[k] = __ldg(psc_initial + k);

#pragma unroll
    for (int j = 0; j < 4; j++) {
        if (zsum[j] == 0.0f) continue;

        float c[NB];
#pragma unroll
        for (int k = 0; k < NB; k++)
            c[k] = we[j] * __ldg(f + (size_t)(el + j) * NB + k) * pi[k];

#pragma unroll
        for (int b = 0; b < BATCH; b++) {
            if (zv[j * 4 + b] != 0.0f) {
                float* base = out_pr + (size_t)b * N_NEUR * NB + (size_t)qe[j] * NB;
#pragma unroll
                for (int k = 0; k < NB; k++)
                    atomicAdd(base + k, c[k]);   // spike value is exactly 1.0f
            }
        }
    }
}

// ---------------------------------------------------------------------------
extern "C" void kernel_launch(void* const* d_in, const int* in_sizes, int n_in,
                              void* d_out, int out_size)
{
    const float* z_buf          = (const float*)d_in[0];
    const float* v              = (const float*)d_in[1];
    const float* r              = (const float*)d_in[2];
    const float* asc_1          = (const float*)d_in[3];
    const float* asc_2          = (const float*)d_in[4];
    const float* psc_rise       = (const float*)d_in[5];
    const float* psc            = (const float*)d_in[6];
    const float* lgn_x          = (const float*)d_in[7];
    const float* bkg_x          = (const float*)d_in[8];
    const float* rec_w          = (const float*)d_in[9];
    const float* rec_factors    = (const float*)d_in[10];
    const float* lgn_w          = (const float*)d_in[11];
    const float* lgn_factors    = (const float*)d_in[12];
    const float* bkg_w          = (const float*)d_in[13];
    const float* bkg_factors    = (const float*)d_in[14];
    const float* decay          = (const float*)d_in[15];
    const float* current_factor = (const float*)d_in[16];
    const float* v_th           = (const float*)d_in[17];
    const float* v_reset        = (const float*)d_in[18];
    const float* e_l            = (const float*)d_in[19];
    const float* g              = (const float*)d_in[20];
    const float* t_ref          = (const float*)d_in[21];
    const float* asc_amps       = (const float*)d_in[22];
    const float* exp_dt_k       = (const float*)d_in[23];
    const float* syn_decay      = (const float*)d_in[24];
    const float* psc_initial    = (const float*)d_in[25];
    const int*   rec_pre        = (const int*)d_in[26];
    const int*   rec_post       = (const int*)d_in[27];
    const int*   lgn_pre        = (const int*)d_in[28];
    const int*   lgn_post       = (const int*)d_in[29];
    const int*   bkg_pre        = (const int*)d_in[30];
    const int*   bkg_post       = (const int*)d_in[31];

    float* out = (float*)d_out;

    const int T = 256;

    // 1) everything elementwise in one pass (initializes the scatter target)
    fused_elementwise_kernel<<<(BN + T - 1) / T, T>>>(z_buf, v, r, asc_1, asc_2,
                                                      psc_rise, psc,
                                                      decay, current_factor, v_th, v_reset,
                                                      e_l, g, t_ref, asc_amps, exp_dt_k,
                                                      syn_decay, out);

    // 2) all three edge lists in one launch, 4 edges/thread
    int quads = E_TOTAL / 4;
    scatter_all_kernel<<<(quads + T - 1) / T, T>>>(z_buf, lgn_x, bkg_x,
                                                   rec_pre, rec_post, rec_w, rec_factors,
                                                   lgn_pre, lgn_post, lgn_w, lgn_factors,
                                                   bkg_pre, bkg_post, bkg_w, bkg_factors,
                                                   psc_initial, out + OFF_PR);
}

// round 6
// speedup vs baseline: 1.8414x; 1.6015x over previous
#include <cuda_runtime.h>
#include <cstdint>

// Problem constants (fixed by the reference)
#define N_NEUR 50000
#define DD     5
#define NB     5
#define DT_C   1.0f
#define BATCH  4
#define E_REC  2000000
#define E_LGN  600000
#define E_BKG  200000
#define NLGN   17400
#define NBKG   100

#define ND        (N_NEUR * DD)              // 250000
#define BN        (BATCH * N_NEUR)           // 200000
#define BNNB      (BATCH * N_NEUR * NB)      // 1000000

// Output layout (floats): z | v | r | asc1 | asc2 | psc_rise | psc | buf
#define OFF_Z    0
#define OFF_V    (BN)
#define OFF_R    (2*BN)
#define OFF_A1   (3*BN)
#define OFF_A2   (4*BN)
#define OFF_PR   (5*BN)
#define OFF_PSC  (5*BN + BNNB)
#define OFF_BUF  (5*BN + 2*BNNB)

#define E_TOTAL  (E_REC + E_LGN + E_BKG)     // 2,800,000 (divisible by 4)

// Spike bitmasks: bit b = neuron fired in batch b. Tiny, L1/L2-resident.
__device__ uint8_t g_mask_rec[ND];
__device__ uint8_t g_mask_lgn[NLGN];
__device__ uint8_t g_mask_bkg[NBKG];

// ---------------------------------------------------------------------------
// Mask build: one thread per pre-neuron across all three source populations.
// Reads are coalesced per batch row; writes are coalesced bytes.
// ---------------------------------------------------------------------------
__global__ void __launch_bounds__(256)
build_mask_kernel(const float* __restrict__ z_buf,
                  const float* __restrict__ lgn_x,
                  const float* __restrict__ bkg_x)
{
    int i = blockIdx.x * blockDim.x + threadIdx.x;
    if (i < ND) {
        unsigned m = 0;
#pragma unroll
        for (int b = 0; b < BATCH; b++)
            m |= (z_buf[(size_t)b * ND + i] > 0.0f) ? (1u << b) : 0u;
        g_mask_rec[i] = (uint8_t)m;
    } else if (i < ND + NLGN) {
        int j = i - ND;
        unsigned m = 0;
#pragma unroll
        for (int b = 0; b < BATCH; b++)
            m |= (lgn_x[(size_t)b * NLGN + j] > 0.0f) ? (1u << b) : 0u;
        g_mask_lgn[j] = (uint8_t)m;
    } else if (i < ND + NLGN + NBKG) {
        int j = i - ND - NLGN;
        unsigned m = 0;
#pragma unroll
        for (int b = 0; b < BATCH; b++)
            m |= (bkg_x[(size_t)b * NBKG + j] > 0.0f) ? (1u << b) : 0u;
        g_mask_bkg[j] = (uint8_t)m;
    }
}

// ---------------------------------------------------------------------------
// Fused elementwise kernel: one thread per (b, n).
//  - new_psc_rise init: out_pr = syn_decay * psc_rise   (scatter adds on top)
//  - new_psc = syn_decay * (psc + DT*psc_rise); input_current = sum_k
//  - GLIF neuron state update (uses OLD asc1/asc2 in c1)
//  - new_buf[:, :N] = new_z ; new_buf[:, N:] = z_buf[:, :4N]
// ---------------------------------------------------------------------------
__global__ void __launch_bounds__(256)
fused_elementwise_kernel(const float* __restrict__ z_buf,
                         const float* __restrict__ v,
                         const float* __restrict__ r,
                         const float* __restrict__ asc1,
                         const float* __restrict__ asc2,
                         const float* __restrict__ psc_rise,
                         const float* __restrict__ psc,
                         const float* __restrict__ decay,
                         const float* __restrict__ current_factor,
                         const float* __restrict__ v_th,
                         const float* __restrict__ v_reset,
                         const float* __restrict__ e_l,
                         const float* __restrict__ g,
                         const float* __restrict__ t_ref,
                         const float* __restrict__ asc_amps,
                         const float* __restrict__ exp_dt_k,
                         const float* __restrict__ syn_decay,
                         float* __restrict__ out)
{
    int idx = blockIdx.x * blockDim.x + threadIdx.x;   // b*N + n
    if (idx >= BN) return;
    int b = idx / N_NEUR;
    int n = idx - b * N_NEUR;

    float sd[NB];
#pragma unroll
    for (int k = 0; k < NB; k++) sd[k] = __ldg(syn_decay + k);

    // psc block: init psc_rise output + new_psc + input current
    size_t po = (size_t)idx * NB;
    float input_current = 0.0f;
#pragma unroll
    for (int k = 0; k < NB; k++) {
        float pr = psc_rise[po + k];
        float pc = psc[po + k];
        out[OFF_PR  + po + k] = sd[k] * pr;               // scatter target
        float np = sd[k] * (pc + DT_C * pr);
        out[OFF_PSC + po + k] = np;
        input_current += np;
    }

    size_t zb_base = (size_t)b * ND;
    float prev_z = z_buf[zb_base + n];

    float a1 = asc1[idx];
    float a2 = asc2[idx];
    float na1 = __ldg(exp_dt_k + 2 * n + 0) * a1 + prev_z * __ldg(asc_amps + 2 * n + 0);
    float na2 = __ldg(exp_dt_k + 2 * n + 1) * a2 + prev_z * __ldg(asc_amps + 2 * n + 1);

    float eln = __ldg(e_l + n);
    float c1  = input_current + a1 + a2 + __ldg(g + n) * eln;
    float nv  = __ldg(decay + n) * v[idx] + __ldg(current_factor + n) * c1;
    if (prev_z > 0.0f) nv = __ldg(v_reset + n);

    float nr = fmaxf(r[idx] + prev_z * __ldg(t_ref + n) - DT_C, 0.0f);

    float vth = __ldg(v_th + n);
    float vsc = (nv - vth) / (vth - eln + 1e-16f);
    float nz  = (vsc > 0.0f && nr <= 0.0f) ? 1.0f : 0.0f;

    out[OFF_Z  + idx] = nz;
    out[OFF_V  + idx] = nv;
    out[OFF_R  + idx] = nr;
    out[OFF_A1 + idx] = na1;
    out[OFF_A2 + idx] = na2;

    // new_buf: front = new_z, rest shifted (all coalesced)
    out[OFF_BUF + zb_base + n] = nz;
#pragma unroll
    for (int d = 0; d < DD - 1; d++)
        out[OFF_BUF + zb_base + (d + 1) * N_NEUR + n] = z_buf[zb_base + d * N_NEUR + n];
}

// ---------------------------------------------------------------------------
// Unified scatter over rec | lgn | bkg. Segment boundaries are multiples of
// 256 quads, so the selector branch is block-uniform. 4 edges/thread via 16B
// vector loads. Spike state comes from the 1-byte-per-neuron bitmask tables
// (4 byte-gathers instead of 16 float-gathers — this kernel was
// L1tex-wavefront-bound on the gathers).
// Spikes are exactly 0/1 (rec_z = 0.4*z + 0.6*z == z in fp32), so a firing
// batch contributes exactly c[k].
// ---------------------------------------------------------------------------
__global__ void __launch_bounds__(256)
scatter_all_kernel(const int*   __restrict__ rp, const int* __restrict__ rq,
                   const float* __restrict__ rw, const float* __restrict__ rf,
                   const int*   __restrict__ lp, const int* __restrict__ lq,
                   const float* __restrict__ lw, const float* __restrict__ lf,
                   const int*   __restrict__ bp, const int* __restrict__ bq,
                   const float* __restrict__ bw, const float* __restrict__ bf,
                   const float* __restrict__ psc_initial,
                   float* __restrict__ out_pr)
{
    int quad = blockIdx.x * blockDim.x + threadIdx.x;
    int e = quad * 4;
    if (e >= E_TOTAL) return;

    const int* pre; const int* post; const float* w; const float* f;
    const uint8_t* mask; int el;
    if (e < E_REC)               { pre = rp; post = rq; w = rw; f = rf; mask = g_mask_rec; el = e; }
    else if (e < E_REC + E_LGN)  { pre = lp; post = lq; w = lw; f = lf; mask = g_mask_lgn; el = e - E_REC; }
    else                         { pre = bp; post = bq; w = bw; f = bf; mask = g_mask_bkg; el = e - E_REC - E_LGN; }

    int4 p4 = *reinterpret_cast<const int4*>(pre + el);

    unsigned m0 = mask[p4.x];
    unsigned m1 = mask[p4.y];
    unsigned m2 = mask[p4.z];
    unsigned m3 = mask[p4.w];
    if ((m0 | m1 | m2 | m3) == 0u) return;

    unsigned m[4] = {m0, m1, m2, m3};

    int4   q4 = *reinterpret_cast<const int4*>(post + el);
    float4 w4 = *reinterpret_cast<const float4*>(w + el);
    int   qe[4] = {q4.x, q4.y, q4.z, q4.w};
    float we[4] = {w4.x, w4.y, w4.z, w4.w};

    float pi[NB];
#pragma unroll
    for (int k = 0; k < NB; k++) pi[k] = __ldg(psc_initial + k);

#pragma unroll
    for (int j = 0; j < 4; j++) {
        if (m[j] == 0u) continue;

        float c[NB];
#pragma unroll
        for (int k = 0; k < NB; k++)
            c[k] = we[j] * __ldg(f + (size_t)(el + j) * NB + k) * pi[k];

#pragma unroll
        for (int b = 0; b < BATCH; b++) {
            if (m[j] & (1u << b)) {
                float* base = out_pr + (size_t)b * N_NEUR * NB + (size_t)qe[j] * NB;
#pragma unroll
                for (int k = 0; k < NB; k++)
                    atomicAdd(base + k, c[k]);   // spike value is exactly 1.0f
            }
        }
    }
}

// ---------------------------------------------------------------------------
extern "C" void kernel_launch(void* const* d_in, const int* in_sizes, int n_in,
                              void* d_out, int out_size)
{
    const float* z_buf          = (const float*)d_in[0];
    const float* v              = (const float*)d_in[1];
    const float* r              = (const float*)d_in[2];
    const float* asc_1          = (const float*)d_in[3];
    const float* asc_2          = (const float*)d_in[4];
    const float* psc_rise       = (const float*)d_in[5];
    const float* psc            = (const float*)d_in[6];
    const float* lgn_x          = (const float*)d_in[7];
    const float* bkg_x          = (const float*)d_in[8];
    const float* rec_w          = (const float*)d_in[9];
    const float* rec_factors    = (const float*)d_in[10];
    const float* lgn_w          = (const float*)d_in[11];
    const float* lgn_factors    = (const float*)d_in[12];
    const float* bkg_w          = (const float*)d_in[13];
    const float* bkg_factors    = (const float*)d_in[14];
    const float* decay          = (const float*)d_in[15];
    const float* current_factor = (const float*)d_in[16];
    const float* v_th           = (const float*)d_in[17];
    const float* v_reset        = (const float*)d_in[18];
    const float* e_l            = (const float*)d_in[19];
    const float* g              = (const float*)d_in[20];
    const float* t_ref          = (const float*)d_in[21];
    const float* asc_amps       = (const float*)d_in[22];
    const float* exp_dt_k       = (const float*)d_in[23];
    const float* syn_decay      = (const float*)d_in[24];
    const float* psc_initial    = (const float*)d_in[25];
    const int*   rec_pre        = (const int*)d_in[26];
    const int*   rec_post       = (const int*)d_in[27];
    const int*   lgn_pre        = (const int*)d_in[28];
    const int*   lgn_post       = (const int*)d_in[29];
    const int*   bkg_pre        = (const int*)d_in[30];
    const int*   bkg_post       = (const int*)d_in[31];

    float* out = (float*)d_out;

    const int T = 256;

    // 1) spike bitmask tables (needed only by the scatter)
    const int MASK_TOTAL = ND + NLGN + NBKG;
    build_mask_kernel<<<(MASK_TOTAL + T - 1) / T, T>>>(z_buf, lgn_x, bkg_x);

    // 2) everything elementwise in one pass (initializes the scatter target)
    fused_elementwise_kernel<<<(BN + T - 1) / T, T>>>(z_buf, v, r, asc_1, asc_2,
                                                      psc_rise, psc,
                                                      decay, current_factor, v_th, v_reset,
                                                      e_l, g, t_ref, asc_amps, exp_dt_k,
                                                      syn_decay, out);

    // 3) all three edge lists in one launch, 4 edges/thread, mask-gated
    int quads = E_TOTAL / 4;
    scatter_all_kernel<<<(quads + T - 1) / T, T>>>(rec_pre, rec_post, rec_w, rec_factors,
                                                   lgn_pre, lgn_post, lgn_w, lgn_factors,
                                                   bkg_pre, bkg_post, bkg_w, bkg_factors,
                                                   psc_initial, out + OFF_PR);
}